// round 12
// baseline (speedup 1.0000x reference)
#include <cuda_runtime.h>
#include <cuda_bf16.h>
#include <math_constants.h>
#include <cstdint>

#define S_LEN 2048
#define DIM   2048
#define NH    32
#define NKVH  8
#define HD    64
#define QDIM  2048
#define KVDIM 512

typedef unsigned short u16;
typedef signed char s8;

// ---------------------------------------------------------------------------
// Scratch
// ---------------------------------------------------------------------------
__device__ __align__(16) float g_Q [S_LEN*QDIM];
__device__ __align__(16) float g_K [S_LEN*KVDIM];
__device__ __align__(16) float g_AO[S_LEN*QDIM];
__device__ __align__(16) u16 g_Qh[S_LEN*QDIM];
__device__ __align__(16) u16 g_Ql[S_LEN*QDIM];
__device__ __align__(16) u16 g_Kh[S_LEN*KVDIM];
__device__ __align__(16) u16 g_Kl[S_LEN*KVDIM];
__device__ __align__(16) u16 g_Vth[KVDIM*S_LEN];
__device__ __align__(16) u16 g_Vtl[KVDIM*S_LEN];
// int8 quant planes + per-row scales
__device__ __align__(16) s8  g_xq1 [S_LEN*DIM];
__device__ __align__(16) s8  g_xq0 [S_LEN*DIM];
__device__ __align__(16) float g_sx [S_LEN];
__device__ __align__(16) s8  g_wq1 [QDIM*DIM];
__device__ __align__(16) s8  g_wq0 [QDIM*DIM];
__device__ __align__(16) float g_swq[QDIM];
__device__ __align__(16) s8  g_wk1 [KVDIM*DIM];
__device__ __align__(16) s8  g_wk0 [KVDIM*DIM];
__device__ __align__(16) float g_swk[KVDIM];
__device__ __align__(16) s8  g_wv1 [KVDIM*DIM];
__device__ __align__(16) s8  g_wv0 [KVDIM*DIM];
__device__ __align__(16) float g_swv[KVDIM];
__device__ __align__(16) s8  g_wo1 [DIM*QDIM];
__device__ __align__(16) s8  g_wo0 [DIM*QDIM];
__device__ __align__(16) float g_swo[DIM];
__device__ __align__(16) s8  g_ao1 [S_LEN*QDIM];
__device__ __align__(16) s8  g_ao0 [S_LEN*QDIM];
__device__ __align__(16) float g_sao[S_LEN];

// ---------------------------------------------------------------------------
// Helpers
// ---------------------------------------------------------------------------
__device__ __forceinline__ u16 tobf(float x) {
    return __bfloat16_as_ushort(__float2bfloat16_rn(x));
}
__device__ __forceinline__ u16 bf_hi(float x, float& lo) {
    u16 h = tobf(x);
    lo = x - __bfloat162float(__ushort_as_bfloat16(h));
    return h;
}
__device__ __forceinline__ uint32_t bfsplit2(float a, float b, float& ra, float& rb)
{
    u16 ha = bf_hi(a, ra);
    u16 hb = bf_hi(b, rb);
    return ((uint32_t)hb << 16) | (uint32_t)ha;
}
__device__ __forceinline__ uint32_t bfpack2(float a, float b)
{
    return ((uint32_t)tobf(b) << 16) | (uint32_t)tobf(a);
}

__device__ __forceinline__ void mma_bf16(float c[4],
    uint32_t a0, uint32_t a1, uint32_t a2, uint32_t a3,
    uint32_t b0, uint32_t b1)
{
    asm volatile(
        "mma.sync.aligned.m16n8k16.row.col.f32.bf16.bf16.f32 "
        "{%0,%1,%2,%3}, {%4,%5,%6,%7}, {%8,%9}, {%0,%1,%2,%3};"
        : "+f"(c[0]), "+f"(c[1]), "+f"(c[2]), "+f"(c[3])
        : "r"(a0), "r"(a1), "r"(a2), "r"(a3), "r"(b0), "r"(b1));
}
__device__ __forceinline__ void mma_s8(int c[4],
    uint32_t a0, uint32_t a1, uint32_t a2, uint32_t a3,
    uint32_t b0, uint32_t b1)
{
    asm volatile(
        "mma.sync.aligned.m16n8k32.row.col.s32.s8.s8.s32 "
        "{%0,%1,%2,%3}, {%4,%5,%6,%7}, {%8,%9}, {%0,%1,%2,%3};"
        : "+r"(c[0]), "+r"(c[1]), "+r"(c[2]), "+r"(c[3])
        : "r"(a0), "r"(a1), "r"(a2), "r"(a3), "r"(b0), "r"(b1));
}

__device__ __forceinline__ void ldsm4(uint32_t& r0, uint32_t& r1,
                                      uint32_t& r2, uint32_t& r3, uint32_t addr)
{
    asm volatile("ldmatrix.sync.aligned.m8n8.x4.shared.b16 {%0,%1,%2,%3}, [%4];"
        : "=r"(r0), "=r"(r1), "=r"(r2), "=r"(r3) : "r"(addr));
}
__device__ __forceinline__ void cp16(uint32_t dst, const void* src)
{
    asm volatile("cp.async.cg.shared.global [%0], [%1], 16;\n" :: "r"(dst), "l"(src));
}
__device__ __forceinline__ void cp_commit() { asm volatile("cp.async.commit_group;\n"); }
__device__ __forceinline__ void cp_wait0()  { asm volatile("cp.async.wait_group 0;\n"); }

// ---------------------------------------------------------------------------
// quant_rows: per-row amax quantization fp32 -> int16 split into 2 int8 planes
// one block per row of 2048 floats
// ---------------------------------------------------------------------------
__global__ __launch_bounds__(256)
void quant_rows(const float* __restrict__ in, s8* __restrict__ q1,
                s8* __restrict__ q0, float* __restrict__ amax_out)
{
    __shared__ float red[8];
    const int row = blockIdx.x;
    const int tid = threadIdx.x;
    const float* rp = in + (size_t)row * 2048;

    float v[8];
    *(float4*)&v[0] = ((const float4*)rp)[tid*2];
    *(float4*)&v[4] = ((const float4*)rp)[tid*2+1];

    float m = 0.f;
    #pragma unroll
    for (int i = 0; i < 8; ++i) m = fmaxf(m, fabsf(v[i]));
    #pragma unroll
    for (int off = 16; off >= 1; off >>= 1)
        m = fmaxf(m, __shfl_xor_sync(0xffffffffu, m, off));
    if ((tid & 31) == 0) red[tid >> 5] = m;
    __syncthreads();
    if (tid == 0) {
        float mm = red[0];
        #pragma unroll
        for (int i = 1; i < 8; ++i) mm = fmaxf(mm, red[i]);
        red[0] = fmaxf(mm, 1e-20f);
    }
    __syncthreads();
    m = red[0];

    const float lam = 32384.f / m;
    uint32_t p1[2] = {0,0}, p0[2] = {0,0};
    #pragma unroll
    for (int i = 0; i < 8; ++i) {
        int Qv = __float2int_rn(v[i] * lam);
        int i1 = (Qv + 128) >> 8;
        int i0 = Qv - (i1 << 8);
        p1[i >> 2] |= ((uint32_t)(i1 & 0xff)) << ((i & 3) * 8);
        p0[i >> 2] |= ((uint32_t)(i0 & 0xff)) << ((i & 3) * 8);
    }
    const size_t off = (size_t)row * 2048 + tid * 8;
    *(uint2*)(q1 + off) = make_uint2(p1[0], p1[1]);
    *(uint2*)(q0 + off) = make_uint2(p0[0], p0[1]);
    if (tid == 0) amax_out[row] = m;
}

// ---------------------------------------------------------------------------
// int8 3-pass NT GEMM:  C = dequant(A_q * B_q^T) + bias
// BM=BN=128, BK=64 (2 x k32 IMMA steps), double-buffered smem.
// Fused multi-weight select: blocks [0,nbq) -> set q, [nbq,nbq+nbk) -> set k,
// rest -> set v (transposed bf16 hi/lo plane output).
// ---------------------------------------------------------------------------
#define GASTR 80
#define GPL   (128*GASTR)
#define GBUF  (4*GPL)
#define GEMM_DYN (2*GBUF)   // 81920
#define QRCP (1.f/(32384.f*32384.f))

__global__ __launch_bounds__(256)
void gemm_s8(const s8* __restrict__ A1, const s8* __restrict__ A0, const float* __restrict__ sA,
             const s8* B1q, const s8* B0q, const float* sBq, const float* bq, float* Cq, int ldcq, int nbq,
             const s8* B1k, const s8* B0k, const float* sBk, const float* bk, float* Ck, int ldck, int nbk,
             const s8* B1v, const s8* B0v, const float* sBv, const float* bv, u16* Vh, u16* Vl)
{
    extern __shared__ char smdyn[];
    const uint32_t sbase = (uint32_t)__cvta_generic_to_shared(smdyn);

    const int tid  = threadIdx.x;
    const int wid  = tid >> 5;
    const int lane = tid & 31;
    const int g    = lane >> 2;
    const int t    = lane & 3;
    const int wm   = (wid & 1) * 64;
    const int wn   = (wid >> 1) * 32;
    const int row0 = blockIdx.y * 128;

    // --- weight-set select ---
    const s8 *B1, *B0; const float *sB, *bias;
    float* C = nullptr; int ldc = 0; bool vmode = false;
    int bx = blockIdx.x;
    if (bx < nbq)            { B1 = B1q; B0 = B0q; sB = sBq; bias = bq; C = Cq; ldc = ldcq; }
    else if (bx < nbq + nbk) { bx -= nbq;       B1 = B1k; B0 = B0k; sB = sBk; bias = bk; C = Ck; ldc = ldck; }
    else                     { bx -= nbq + nbk; B1 = B1v; B0 = B0v; sB = sBv; bias = bv; vmode = true; }
    const int col0 = bx * 128;

    // loader: 2 threads per row, 32B each per plane
    const int lr   = tid >> 1;
    const int half = tid & 1;
    const s8* Ag1 = A1 + (size_t)(row0 + lr) * 2048 + half*32;
    const s8* Ag0 = A0 + (size_t)(row0 + lr) * 2048 + half*32;
    const s8* Bg1 = B1 + (size_t)(col0 + lr) * 2048 + half*32;
    const s8* Bg0 = B0 + (size_t)(col0 + lr) * 2048 + half*32;
    const uint32_t ddst = (uint32_t)(lr * GASTR + half*32);

    int acc1[4][4][4], acc2[4][4][4];
    #pragma unroll
    for (int mt = 0; mt < 4; ++mt)
        #pragma unroll
        for (int nt = 0; nt < 4; ++nt)
            #pragma unroll
            for (int e = 0; e < 4; ++e) { acc1[mt][nt][e] = 0; acc2[mt][nt][e] = 0; }

    const int T = 2048 / 64;

    {
        const uint32_t o = sbase + ddst;
        cp16(o,            Ag1);  cp16(o + 16,           Ag1 + 16);
        cp16(o + GPL,      Ag0);  cp16(o + GPL + 16,     Ag0 + 16);
        cp16(o + 2*GPL,    Bg1);  cp16(o + 2*GPL + 16,   Bg1 + 16);
        cp16(o + 3*GPL,    Bg0);  cp16(o + 3*GPL + 16,   Bg0 + 16);
        cp_commit();
    }

    for (int tt = 0; tt < T; ++tt) {
        const int cur = tt & 1;
        if (tt + 1 < T) {
            const int k0 = (tt + 1) * 64;
            const uint32_t o = sbase + (cur ^ 1) * GBUF + ddst;
            cp16(o,          Ag1 + k0);  cp16(o + 16,          Ag1 + k0 + 16);
            cp16(o + GPL,    Ag0 + k0);  cp16(o + GPL + 16,    Ag0 + k0 + 16);
            cp16(o + 2*GPL,  Bg1 + k0);  cp16(o + 2*GPL + 16,  Bg1 + k0 + 16);
            cp16(o + 3*GPL,  Bg0 + k0);  cp16(o + 3*GPL + 16,  Bg0 + k0 + 16);
            cp_commit();
            asm volatile("cp.async.wait_group 1;\n");
        } else {
            cp_wait0();
        }
        __syncthreads();

        const uint32_t bufA = sbase + cur * GBUF;
        const uint32_t bufB = bufA + 2*GPL;

        #pragma unroll
        for (int kk = 0; kk < 2; ++kk) {
            const uint32_t kof = kk * 32;
            uint32_t a1[4][4], a0[4][4];
            #pragma unroll
            for (int mt = 0; mt < 4; ++mt) {
                uint32_t addr = bufA + (uint32_t)((wm + mt*16 + (lane & 15)) * GASTR)
                              + kof + ((lane >> 4) * 16);
                ldsm4(a1[mt][0], a1[mt][1], a1[mt][2], a1[mt][3], addr);
                ldsm4(a0[mt][0], a0[mt][1], a0[mt][2], a0[mt][3], addr + GPL);
            }
            uint32_t b1[4][2], b0[4][2];
            #pragma unroll
            for (int p = 0; p < 2; ++p) {
                uint32_t addr = bufB + (uint32_t)((wn + p*16 + (lane & 7) + ((lane >> 4) << 3)) * GASTR)
                              + kof + (((lane >> 3) & 1) * 16);
                ldsm4(b1[2*p][0], b1[2*p][1], b1[2*p+1][0], b1[2*p+1][1], addr);
                ldsm4(b0[2*p][0], b0[2*p][1], b0[2*p+1][0], b0[2*p+1][1], addr + GPL);
            }
            #pragma unroll
            for (int mt = 0; mt < 4; ++mt)
                #pragma unroll
                for (int nt = 0; nt < 4; ++nt)
                    mma_s8(acc1[mt][nt], a1[mt][0], a1[mt][1], a1[mt][2], a1[mt][3],
                           b1[nt][0], b1[nt][1]);
            #pragma unroll
            for (int mt = 0; mt < 4; ++mt)
                #pragma unroll
                for (int nt = 0; nt < 4; ++nt)
                    mma_s8(acc2[mt][nt], a1[mt][0], a1[mt][1], a1[mt][2], a1[mt][3],
                           b0[nt][0], b0[nt][1]);
            #pragma unroll
            for (int mt = 0; mt < 4; ++mt)
                #pragma unroll
                for (int nt = 0; nt < 4; ++nt)
                    mma_s8(acc2[mt][nt], a0[mt][0], a0[mt][1], a0[mt][2], a0[mt][3],
                           b1[nt][0], b1[nt][1]);
        }
        __syncthreads();
    }

    // epilogue: dequant + bias
    #pragma unroll
    for (int mt = 0; mt < 4; ++mt) {
        const int r  = row0 + wm + mt*16 + g;
        const float sa0 = sA[r] * QRCP;
        const float sa1 = sA[r + 8] * QRCP;
        #pragma unroll
        for (int nt = 0; nt < 4; ++nt) {
            const int c = col0 + wn + nt*8 + 2*t;
            const float sc0 = sB[c], sc1 = sB[c+1];
            float v00 = ((float)acc1[mt][nt][0]*65536.f + (float)acc2[mt][nt][0]*256.f) * sa0 * sc0 + bias[c];
            float v01 = ((float)acc1[mt][nt][1]*65536.f + (float)acc2[mt][nt][1]*256.f) * sa0 * sc1 + bias[c+1];
            float v10 = ((float)acc1[mt][nt][2]*65536.f + (float)acc2[mt][nt][2]*256.f) * sa1 * sc0 + bias[c];
            float v11 = ((float)acc1[mt][nt][3]*65536.f + (float)acc2[mt][nt][3]*256.f) * sa1 * sc1 + bias[c+1];
            if (!vmode) {
                *(float2*)&C[(size_t)r       * ldc + c] = make_float2(v00, v01);
                *(float2*)&C[(size_t)(r + 8) * ldc + c] = make_float2(v10, v11);
            } else {
                float l;
                Vh[(size_t)c     * S_LEN + r    ] = bf_hi(v00, l); Vl[(size_t)c     * S_LEN + r    ] = tobf(l);
                Vh[(size_t)(c+1) * S_LEN + r    ] = bf_hi(v01, l); Vl[(size_t)(c+1) * S_LEN + r    ] = tobf(l);
                Vh[(size_t)c     * S_LEN + r + 8] = bf_hi(v10, l); Vl[(size_t)c     * S_LEN + r + 8] = tobf(l);
                Vh[(size_t)(c+1) * S_LEN + r + 8] = bf_hi(v11, l); Vl[(size_t)(c+1) * S_LEN + r + 8] = tobf(l);
            }
        }
    }
}

// ---------------------------------------------------------------------------
// RoPE + split (fp32 -> bf16 hi/lo planes)
// ---------------------------------------------------------------------------
__global__ void rope_split_kernel(const float* __restrict__ T, const float* __restrict__ rope,
                                  u16* __restrict__ Th, u16* __restrict__ Tl,
                                  int nheads, int ld)
{
    int idx = blockIdx.x * blockDim.x + threadIdx.x;
    int d  = idx & 31;
    int sh = idx >> 5;
    int h  = sh % nheads;
    int s  = sh / nheads;
    if (s >= S_LEN) return;
    float c  = rope[s*128 + d];
    float sn = rope[s*128 + 64 + d];
    const float* p = T + (size_t)s * ld + h*HD + d;
    float x0 = p[0], x1 = p[32];
    float y0 = fmaf(x0, c, -x1*sn);
    float y1 = fmaf(x1, c,  x0*sn);
    int b = s*ld + h*HD + d;
    float l;
    Th[b]      = bf_hi(y0, l);  Tl[b]      = tobf(l);
    Th[b + 32] = bf_hi(y1, l);  Tl[b + 32] = tobf(l);
}

// ---------------------------------------------------------------------------
// bf16x3 flash attention (fp32 AO output)
// ---------------------------------------------------------------------------
#define QSTR 144
#define KVPL (64*QSTR)
#define ATT_DYN (128*QSTR*2)

__global__ __launch_bounds__(256)
void attn_kernel(const u16* __restrict__ Qh, const u16* __restrict__ Ql,
                 const u16* __restrict__ Kh, const u16* __restrict__ Kl,
                 const u16* __restrict__ Vth, const u16* __restrict__ Vtl,
                 const float* __restrict__ sinks, float* __restrict__ AO)
{
    extern __shared__ char sm[];
    const uint32_t sb  = (uint32_t)__cvta_generic_to_shared(sm);
    const uint32_t sKH = sb, sVH = sb + 2*KVPL;

    const int h    = blockIdx.y;
    const int qi   = (int)gridDim.x - 1 - (int)blockIdx.x;
    const int s0   = qi * 128;
    const int kvh  = h >> 2;
    const int tid  = threadIdx.x;
    const int w    = tid >> 5;
    const int lane = tid & 31;
    const int g    = lane >> 2;
    const int t    = lane & 3;
    const int wrow = w * 16;

    {
        const int r    = tid >> 1;
        const int half = tid & 1;
        const u16* qgh = Qh + (size_t)(s0 + r) * QDIM + h*HD + half*32;
        const u16* qgl = Ql + (size_t)(s0 + r) * QDIM + h*HD + half*32;
        const uint32_t d = sb + (uint32_t)(r * QSTR + half*64);
        #pragma unroll
        for (int i = 0; i < 4; ++i) {
            cp16(d + 16*i, qgh + 8*i);
            cp16(d + 128*QSTR + 16*i, qgl + 8*i);
        }
        cp_commit();
        cp_wait0();
    }
    __syncthreads();

    uint32_t qh[4][4], ql[4][4];
    #pragma unroll
    for (int kt = 0; kt < 4; ++kt) {
        uint32_t addr = sb + (uint32_t)((wrow + (lane & 15)) * QSTR) + kt*32 + ((lane >> 4) * 16);
        ldsm4(qh[kt][0], qh[kt][1], qh[kt][2], qh[kt][3], addr);
        ldsm4(ql[kt][0], ql[kt][1], ql[kt][2], ql[kt][3], addr + 128*QSTR);
    }
    __syncthreads();

    float m0 = -CUDART_INF_F, m1 = -CUDART_INF_F;
    float l0 = 0.f, l1 = 0.f;
    float o[8][4];
    #pragma unroll
    for (int nt = 0; nt < 8; ++nt)
        #pragma unroll
        for (int e = 0; e < 4; ++e) o[nt][e] = 0.f;

    const float scale = 0.125f;
    const int kb_end = 2*qi + 2;

    for (int kb = 0; kb < kb_end; ++kb) {
        const int ks0 = kb * 64;

        {
            const int r  = tid >> 2;
            const int q4 = tid & 3;
            const u16* kgh = Kh  + (size_t)(ks0 + r) * KVDIM + kvh*HD + q4*16;
            const u16* kgl = Kl  + (size_t)(ks0 + r) * KVDIM + kvh*HD + q4*16;
            const u16* vgh = Vth + (size_t)(kvh*HD + r) * S_LEN + ks0 + q4*16;
            const u16* vgl = Vtl + (size_t)(kvh*HD + r) * S_LEN + ks0 + q4*16;
            const uint32_t d = (uint32_t)(r * QSTR + q4*32);
            cp16(sKH + d, kgh); cp16(sKH + d + 16, kgh + 8);
            cp16(sKH + KVPL + d, kgl); cp16(sKH + KVPL + d + 16, kgl + 8);
            cp16(sVH + d, vgh); cp16(sVH + d + 16, vgh + 8);
            cp16(sVH + KVPL + d, vgl); cp16(sVH + KVPL + d + 16, vgl + 8);
            cp_commit();
            cp_wait0();
        }
        __syncthreads();

        const bool skip = (ks0 > s0 + wrow + 15);
        if (!skip) {
            float s[8][4];
            #pragma unroll
            for (int nt = 0; nt < 8; ++nt)
                #pragma unroll
                for (int e = 0; e < 4; ++e) s[nt][e] = 0.f;

            #pragma unroll
            for (int kt = 0; kt < 4; ++kt) {
                uint32_t bh[8][2], bl[8][2];
                #pragma unroll
                for (int p = 0; p < 4; ++p) {
                    uint32_t addr = sKH + (uint32_t)((p*16 + (lane & 7) + ((lane >> 4) << 3)) * QSTR)
                                  + kt*32 + (((lane >> 3) & 1) * 16);
                    ldsm4(bh[2*p][0], bh[2*p][1], bh[2*p+1][0], bh[2*p+1][1], addr);
                    ldsm4(bl[2*p][0], bl[2*p][1], bl[2*p+1][0], bl[2*p+1][1], addr + KVPL);
                }
                #pragma unroll
                for (int nt = 0; nt < 8; ++nt) {
                    mma_bf16(s[nt], qh[kt][0], qh[kt][1], qh[kt][2], qh[kt][3], bh[nt][0], bh[nt][1]);
                    mma_bf16(s[nt], qh[kt][0], qh[kt][1], qh[kt][2], qh[kt][3], bl[nt][0], bl[nt][1]);
                    mma_bf16(s[nt], ql[kt][0], ql[kt][1], ql[kt][2], ql[kt][3], bh[nt][0], bh[nt][1]);
                }
            }

            const bool need_mask = (ks0 + 63 > s0 + wrow);
            const int row0g = s0 + wrow + g;
            #pragma unroll
            for (int nt = 0; nt < 8; ++nt) {
                #pragma unroll
                for (int e = 0; e < 4; ++e) s[nt][e] *= scale;
                if (need_mask) {
                    const int c = ks0 + nt*8 + 2*t;
                    if (c     > row0g    ) s[nt][0] = -CUDART_INF_F;
                    if (c + 1 > row0g    ) s[nt][1] = -CUDART_INF_F;
                    if (c     > row0g + 8) s[nt][2] = -CUDART_INF_F;
                    if (c + 1 > row0g + 8) s[nt][3] = -CUDART_INF_F;
                }
            }

            float mx0 = -CUDART_INF_F, mx1 = -CUDART_INF_F;
            #pragma unroll
            for (int nt = 0; nt < 8; ++nt) {
                mx0 = fmaxf(mx0, fmaxf(s[nt][0], s[nt][1]));
                mx1 = fmaxf(mx1, fmaxf(s[nt][2], s[nt][3]));
            }
            mx0 = fmaxf(mx0, __shfl_xor_sync(0xffffffffu, mx0, 1));
            mx0 = fmaxf(mx0, __shfl_xor_sync(0xffffffffu, mx0, 2));
            mx1 = fmaxf(mx1, __shfl_xor_sync(0xffffffffu, mx1, 1));
            mx1 = fmaxf(mx1, __shfl_xor_sync(0xffffffffu, mx1, 2));

            float mn0 = fmaxf(m0, mx0), mn1 = fmaxf(m1, mx1);
            float corr0 = __expf(m0 - mn0), corr1 = __expf(m1 - mn1);

            float ps0 = 0.f, ps1 = 0.f;
            #pragma unroll
            for (int nt = 0; nt < 8; ++nt) {
                s[nt][0] = __expf(s[nt][0] - mn0);
                s[nt][1] = __expf(s[nt][1] - mn0);
                s[nt][2] = __expf(s[nt][2] - mn1);
                s[nt][3] = __expf(s[nt][3] - mn1);
                ps0 += s[nt][0] + s[nt][1];
                ps1 += s[nt][2] + s[nt][3];
            }
            ps0 += __shfl_xor_sync(0xffffffffu, ps0, 1);
            ps0 += __shfl_xor_sync(0xffffffffu, ps0, 2);
            ps1 += __shfl_xor_sync(0xffffffffu, ps1, 1);
            ps1 += __shfl_xor_sync(0xffffffffu, ps1, 2);

            l0 = l0 * corr0 + ps0;  m0 = mn0;
            l1 = l1 * corr1 + ps1;  m1 = mn1;

            #pragma unroll
            for (int nt = 0; nt < 8; ++nt) {
                o[nt][0] *= corr0; o[nt][1] *= corr0;
                o[nt][2] *= corr1; o[nt][3] *= corr1;
            }

            #pragma unroll
            for (int kt = 0; kt < 4; ++kt) {
                float r0, r1;
                uint32_t ah0 = bfsplit2(s[2*kt  ][0], s[2*kt  ][1], r0, r1);
                uint32_t al0 = bfpack2(r0, r1);
                uint32_t ah1 = bfsplit2(s[2*kt  ][2], s[2*kt  ][3], r0, r1);
                uint32_t al1 = bfpack2(r0, r1);
                uint32_t ah2 = bfsplit2(s[2*kt+1][0], s[2*kt+1][1], r0, r1);
                uint32_t al2 = bfpack2(r0, r1);
                uint32_t ah3 = bfsplit2(s[2*kt+1][2], s[2*kt+1][3], r0, r1);
                uint32_t al3 = bfpack2(r0, r1);

                uint32_t vh[8][2], vl[8][2];
                #pragma unroll
                for (int p = 0; p < 4; ++p) {
                    uint32_t addr = sVH + (uint32_t)((p*16 + (lane & 7) + ((lane >> 4) << 3)) * QSTR)
                                  + kt*32 + (((lane >> 3) & 1) * 16);
                    ldsm4(vh[2*p][0], vh[2*p][1], vh[2*p+1][0], vh[2*p+1][1], addr);
                    ldsm4(vl[2*p][0], vl[2*p][1], vl[2*p+1][0], vl[2*p+1][1], addr + KVPL);
                }
                #pragma unroll
                for (int nt = 0; nt < 8; ++nt) {
                    mma_bf16(o[nt], ah0, ah1, ah2, ah3, vh[nt][0], vh[nt][1]);
                    mma_bf16(o[nt], ah0, ah1, ah2, ah3, vl[nt][0], vl[nt][1]);
                    mma_bf16(o[nt], al0, al1, al2, al3, vh[nt][0], vh[nt][1]);
                }
            }
        }
        __syncthreads();
    }

    const float sink = sinks[h];
    float lse0 = m0 + __logf(l0);
    float lse1 = m1 + __logf(l1);
    float cb0 = fmaxf(lse0, sink) + log1pf(__expf(-fabsf(lse0 - sink)));
    float cb1 = fmaxf(lse1, sink) + log1pf(__expf(-fabsf(lse1 - sink)));
    float inv0 = __expf(fmaxf(lse0 - cb0, -20.f)) / l0;
    float inv1 = __expf(fmaxf(lse1 - cb1, -20.f)) / l1;

    const int r0i = s0 + wrow + g;
    #pragma unroll
    for (int nt = 0; nt < 8; ++nt) {
        const int c = h*HD + nt*8 + 2*t;
        *(float2*)&AO[(size_t)r0i       * QDIM + c] = make_float2(o[nt][0]*inv0, o[nt][1]*inv0);
        *(float2*)&AO[(size_t)(r0i + 8) * QDIM + c] = make_float2(o[nt][2]*inv1, o[nt][3]*inv1);
    }
}

// ---------------------------------------------------------------------------
// Launch
// ---------------------------------------------------------------------------
extern "C" void kernel_launch(void* const* d_in, const int* in_sizes, int n_in,
                              void* d_out, int out_size)
{
    const float* x     = (const float*)d_in[0];
    const float* rope  = (const float*)d_in[1];
    const float* wq_w  = (const float*)d_in[2];
    const float* wq_b  = (const float*)d_in[3];
    const float* wk_w  = (const float*)d_in[4];
    const float* wk_b  = (const float*)d_in[5];
    const float* wv_w  = (const float*)d_in[6];
    const float* wv_b  = (const float*)d_in[7];
    const float* wo_w  = (const float*)d_in[8];
    const float* wo_b  = (const float*)d_in[9];
    const float* sinks = (const float*)d_in[10];
    float* out = (float*)d_out;

#define SYM(p, s) do { void* _q; cudaGetSymbolAddress(&_q, s); p = decltype(p)(_q); } while (0)
    float *Q, *K, *AO;
    u16 *Qh,*Ql,*Kh,*Kl,*Vth,*Vtl;
    s8 *xq1,*xq0,*wq1,*wq0,*wk1,*wk0,*wv1,*wv0,*wo1,*wo0,*ao1,*ao0;
    float *sx,*swq,*swk,*swv,*swo,*sao;
    SYM(Q, g_Q);   SYM(K, g_K);  SYM(AO, g_AO);
    SYM(Qh, g_Qh); SYM(Ql, g_Ql); SYM(Kh, g_Kh); SYM(Kl, g_Kl);
    SYM(Vth, g_Vth); SYM(Vtl, g_Vtl);
    SYM(xq1, g_xq1); SYM(xq0, g_xq0); SYM(sx, g_sx);
    SYM(wq1, g_wq1); SYM(wq0, g_wq0); SYM(swq, g_swq);
    SYM(wk1, g_wk1); SYM(wk0, g_wk0); SYM(swk, g_swk);
    SYM(wv1, g_wv1); SYM(wv0, g_wv0); SYM(swv, g_swv);
    SYM(wo1, g_wo1); SYM(wo0, g_wo0); SYM(swo, g_swo);
    SYM(ao1, g_ao1); SYM(ao0, g_ao0); SYM(sao, g_sao);
#undef SYM

    cudaFuncSetAttribute(gemm_s8, cudaFuncAttributeMaxDynamicSharedMemorySize, GEMM_DYN);

    // quantize inputs (per-row int16 -> q1/q0 int8 planes)
    quant_rows<<<S_LEN, 256>>>(x,    xq1, xq0, sx);
    quant_rows<<<QDIM,  256>>>(wq_w, wq1, wq0, swq);
    quant_rows<<<KVDIM, 256>>>(wk_w, wk1, wk0, swk);
    quant_rows<<<KVDIM, 256>>>(wv_w, wv1, wv0, swv);
    quant_rows<<<DIM,   256>>>(wo_w, wo1, wo0, swo);

    // fused QKV projection: blocks 0-15 Q, 16-19 K, 20-23 V
    gemm_s8<<<dim3(24, S_LEN/128), 256, GEMM_DYN>>>(
        xq1, xq0, sx,
        wq1, wq0, swq, wq_b, Q, QDIM, 16,
        wk1, wk0, swk, wk_b, K, KVDIM, 4,
        wv1, wv0, swv, wv_b, Vth, Vtl);

    // rope + bf16 split for attention
    rope_split_kernel<<<(S_LEN*NH  *32)/256, 256>>>(Q, rope, Qh, Ql, NH,   QDIM);
    rope_split_kernel<<<(S_LEN*NKVH*32)/256, 256>>>(K, rope, Kh, Kl, NKVH, KVDIM);

    // attention (bf16x3) -> fp32 AO
    attn_kernel<<<dim3(S_LEN/128, NH), 256, ATT_DYN>>>(Qh, Ql, Kh, Kl, Vth, Vtl, sinks, AO);

    // quantize AO, then int8 output projection
    quant_rows<<<S_LEN, 256>>>(AO, ao1, ao0, sao);
    gemm_s8<<<dim3(16, S_LEN/128), 256, GEMM_DYN>>>(
        ao1, ao0, sao,
        wo1, wo0, swo, wo_b, out, DIM, 16,
        nullptr, nullptr, nullptr, nullptr, nullptr, 0, 0,
        nullptr, nullptr, nullptr, nullptr, nullptr, nullptr);
}

// round 16
// speedup vs baseline: 1.6677x; 1.6677x over previous
#include <cuda_runtime.h>
#include <cuda_fp16.h>
#include <math_constants.h>
#include <cstdint>

#define S_LEN 2048
#define DIM   2048
#define NH    32
#define NKVH  8
#define HD    64
#define QDIM  2048
#define KVDIM 512

typedef unsigned short u16;

// ---------------------------------------------------------------------------
// Scratch (fp16 planes)
// ---------------------------------------------------------------------------
__device__ __align__(16) float g_Q [S_LEN*QDIM];     // fp32 Q pre-rope
__device__ __align__(16) float g_K [S_LEN*KVDIM];    // fp32 K pre-rope
__device__ __align__(16) u16 g_Qh[S_LEN*QDIM];
__device__ __align__(16) u16 g_Ql[S_LEN*QDIM];
__device__ __align__(16) u16 g_Kh[S_LEN*KVDIM];
__device__ __align__(16) u16 g_Vth[KVDIM*S_LEN];     // V^T plane [hd][seq]
__device__ __align__(16) u16 g_AOh[S_LEN*QDIM];
__device__ __align__(16) u16 g_AOl[S_LEN*QDIM];
__device__ __align__(16) u16 g_xh[S_LEN*DIM];
__device__ __align__(16) u16 g_xl[S_LEN*DIM];
__device__ __align__(16) u16 g_wqh[QDIM*DIM];
__device__ __align__(16) u16 g_wkh[KVDIM*DIM];
__device__ __align__(16) u16 g_wvh[KVDIM*DIM];
__device__ __align__(16) u16 g_woh[DIM*QDIM];

// ---------------------------------------------------------------------------
// fp16 helpers
// ---------------------------------------------------------------------------
__device__ __forceinline__ u16 toh(float x) {
    return __half_as_ushort(__float2half_rn(x));
}
__device__ __forceinline__ u16 h_hi(float x, float& lo) {
    u16 h = toh(x);
    lo = x - __half2float(__ushort_as_half(h));
    return h;
}
__device__ __forceinline__ uint32_t hsplit2(float a, float b, float& ra, float& rb)
{
    u16 ha = h_hi(a, ra);
    u16 hb = h_hi(b, rb);
    return ((uint32_t)hb << 16) | (uint32_t)ha;
}
__device__ __forceinline__ uint32_t hpack2(float a, float b)
{
    return ((uint32_t)toh(b) << 16) | (uint32_t)toh(a);
}

__device__ __forceinline__ void mma_f16(float c[4],
    uint32_t a0, uint32_t a1, uint32_t a2, uint32_t a3,
    uint32_t b0, uint32_t b1)
{
    asm volatile(
        "mma.sync.aligned.m16n8k16.row.col.f32.f16.f16.f32 "
        "{%0,%1,%2,%3}, {%4,%5,%6,%7}, {%8,%9}, {%0,%1,%2,%3};"
        : "+f"(c[0]), "+f"(c[1]), "+f"(c[2]), "+f"(c[3])
        : "r"(a0), "r"(a1), "r"(a2), "r"(a3), "r"(b0), "r"(b1));
}

__device__ __forceinline__ void ldsm4(uint32_t& r0, uint32_t& r1,
                                      uint32_t& r2, uint32_t& r3, uint32_t addr)
{
    asm volatile("ldmatrix.sync.aligned.m8n8.x4.shared.b16 {%0,%1,%2,%3}, [%4];"
        : "=r"(r0), "=r"(r1), "=r"(r2), "=r"(r3) : "r"(addr));
}
__device__ __forceinline__ void cp16(uint32_t dst, const void* src)
{
    asm volatile("cp.async.cg.shared.global [%0], [%1], 16;\n" :: "r"(dst), "l"(src));
}
__device__ __forceinline__ void cp_commit() { asm volatile("cp.async.commit_group;\n"); }
__device__ __forceinline__ void cp_wait0()  { asm volatile("cp.async.wait_group 0;\n"); }

// ---------------------------------------------------------------------------
// split16: fp32 -> fp16 hi + residual planes
// ---------------------------------------------------------------------------
__global__ void split16_kernel(const float* __restrict__ in, u16* __restrict__ hi,
                               u16* __restrict__ lo, int n4)
{
    int i = blockIdx.x * blockDim.x + threadIdx.x;
    if (i >= n4) return;
    float4 v = ((const float4*)in)[i];
    float l0, l1, l2, l3;
    ushort4 H, L;
    H.x = h_hi(v.x, l0); H.y = h_hi(v.y, l1);
    H.z = h_hi(v.z, l2); H.w = h_hi(v.w, l3);
    L.x = toh(l0); L.y = toh(l1); L.z = toh(l2); L.w = toh(l3);
    ((ushort4*)hi)[i] = H;
    ((ushort4*)lo)[i] = L;
}

// conv16: fp32 -> fp16 single plane
__global__ void conv16_kernel(const float* __restrict__ in, u16* __restrict__ hi, int n4)
{
    int i = blockIdx.x * blockDim.x + threadIdx.x;
    if (i >= n4) return;
    float4 v = ((const float4*)in)[i];
    ushort4 H;
    H.x = toh(v.x); H.y = toh(v.y); H.z = toh(v.z); H.w = toh(v.w);
    ((ushort4*)hi)[i] = H;
}

// ---------------------------------------------------------------------------
// fp16x2 NT GEMM (2 passes: Ah*Bh + Al*Bh):  C = A * B^T + bias
// BM=BN=128, BK=32, 256 threads (8 warps 2x4), ldmatrix fragments.
// 3 smem planes (Ah, Al, Bh), double buffered.
// ---------------------------------------------------------------------------
#define GASTR 80
#define GPL   (128*GASTR)       // 10240
#define GBUF  (3*GPL)           // 30720
#define GEMM_DYN (2*GBUF)       // 61440

__global__ __launch_bounds__(256)
void gemm_f16(const u16* __restrict__ Ah, const u16* __restrict__ Al,
              const u16* B_q, const float* bq, float* Cq, int ldcq, int nbq,
              const u16* B_k, const float* bk, float* Ck, int ldck, int nbk,
              const u16* B_v, const float* bv, u16* Vh)
{
    extern __shared__ char smdyn[];
    const uint32_t sbase = (uint32_t)__cvta_generic_to_shared(smdyn);

    const int tid  = threadIdx.x;
    const int wid  = tid >> 5;
    const int lane = tid & 31;
    const int g    = lane >> 2;
    const int t    = lane & 3;
    const int wm   = (wid & 1) * 64;
    const int wn   = (wid >> 1) * 32;
    const int row0 = blockIdx.y * 128;

    const u16* B; const float* bias;
    float* C = nullptr; int ldc = 0; bool vmode = false;
    int bx = blockIdx.x;
    if (bx < nbq)            { B = B_q; bias = bq; C = Cq; ldc = ldcq; }
    else if (bx < nbq + nbk) { bx -= nbq;       B = B_k; bias = bk; C = Ck; ldc = ldck; }
    else                     { bx -= nbq + nbk; B = B_v; bias = bv; vmode = true; }
    const int col0 = bx * 128;

    // loader: 2 threads per row, 32B (16 elems) each per plane
    const int lr   = tid >> 1;
    const int half = tid & 1;
    const u16* Agh = Ah + (size_t)(row0 + lr) * 2048 + half*16;
    const u16* Agl = Al + (size_t)(row0 + lr) * 2048 + half*16;
    const u16* Bg  = B  + (size_t)(col0 + lr) * 2048 + half*16;
    const uint32_t ddst = (uint32_t)(lr * GASTR + half*32);

    float acc[4][4][4];
    #pragma unroll
    for (int mt = 0; mt < 4; ++mt)
        #pragma unroll
        for (int nt = 0; nt < 4; ++nt)
            #pragma unroll
            for (int e = 0; e < 4; ++e) acc[mt][nt][e] = 0.f;

    const int T = 2048 / 32;

    {
        const uint32_t o = sbase + ddst;
        cp16(o,              Agh);  cp16(o + 16,           Agh + 8);
        cp16(o + GPL,        Agl);  cp16(o + GPL + 16,     Agl + 8);
        cp16(o + 2*GPL,      Bg );  cp16(o + 2*GPL + 16,   Bg  + 8);
        cp_commit();
    }

    for (int tt = 0; tt < T; ++tt) {
        const int cur = tt & 1;
        if (tt + 1 < T) {
            const int k0 = (tt + 1) * 32;
            const uint32_t o = sbase + (cur ^ 1) * GBUF + ddst;
            cp16(o,            Agh + k0);  cp16(o + 16,          Agh + k0 + 8);
            cp16(o + GPL,      Agl + k0);  cp16(o + GPL + 16,    Agl + k0 + 8);
            cp16(o + 2*GPL,    Bg  + k0);  cp16(o + 2*GPL + 16,  Bg  + k0 + 8);
            cp_commit();
            asm volatile("cp.async.wait_group 1;\n");
        } else {
            cp_wait0();
        }
        __syncthreads();

        const uint32_t bufA = sbase + cur * GBUF;
        const uint32_t bufB = bufA + 2*GPL;

        #pragma unroll
        for (int kk = 0; kk < 2; ++kk) {
            const uint32_t kof = kk * 32;
            uint32_t ah[4][4], al[4][4];
            #pragma unroll
            for (int mt = 0; mt < 4; ++mt) {
                uint32_t addr = bufA + (uint32_t)((wm + mt*16 + (lane & 15)) * GASTR)
                              + kof + ((lane >> 4) * 16);
                ldsm4(ah[mt][0], ah[mt][1], ah[mt][2], ah[mt][3], addr);
                ldsm4(al[mt][0], al[mt][1], al[mt][2], al[mt][3], addr + GPL);
            }
            uint32_t bh[4][2];
            #pragma unroll
            for (int p = 0; p < 2; ++p) {
                uint32_t addr = bufB + (uint32_t)((wn + p*16 + (lane & 7) + ((lane >> 4) << 3)) * GASTR)
                              + kof + (((lane >> 3) & 1) * 16);
                ldsm4(bh[2*p][0], bh[2*p][1], bh[2*p+1][0], bh[2*p+1][1], addr);
            }
            #pragma unroll
            for (int mt = 0; mt < 4; ++mt)
                #pragma unroll
                for (int nt = 0; nt < 4; ++nt)
                    mma_f16(acc[mt][nt], ah[mt][0], ah[mt][1], ah[mt][2], ah[mt][3],
                            bh[nt][0], bh[nt][1]);
            #pragma unroll
            for (int mt = 0; mt < 4; ++mt)
                #pragma unroll
                for (int nt = 0; nt < 4; ++nt)
                    mma_f16(acc[mt][nt], al[mt][0], al[mt][1], al[mt][2], al[mt][3],
                            bh[nt][0], bh[nt][1]);
        }
        __syncthreads();
    }

    #pragma unroll
    for (int mt = 0; mt < 4; ++mt) {
        const int r = row0 + wm + mt*16 + g;
        #pragma unroll
        for (int nt = 0; nt < 4; ++nt) {
            const int c = col0 + wn + nt*8 + 2*t;
            float v00 = acc[mt][nt][0] + bias[c];
            float v01 = acc[mt][nt][1] + bias[c+1];
            float v10 = acc[mt][nt][2] + bias[c];
            float v11 = acc[mt][nt][3] + bias[c+1];
            if (!vmode) {
                *(float2*)&C[(size_t)r       * ldc + c] = make_float2(v00, v01);
                *(float2*)&C[(size_t)(r + 8) * ldc + c] = make_float2(v10, v11);
            } else {
                Vh[(size_t)c     * S_LEN + r    ] = toh(v00);
                Vh[(size_t)(c+1) * S_LEN + r    ] = toh(v01);
                Vh[(size_t)c     * S_LEN + r + 8] = toh(v10);
                Vh[(size_t)(c+1) * S_LEN + r + 8] = toh(v11);
            }
        }
    }
}

// ---------------------------------------------------------------------------
// RoPE + split. For Q: hi+lo planes. For K: hi plane only.
// ---------------------------------------------------------------------------
__global__ void rope_split_kernel(const float* __restrict__ T, const float* __restrict__ rope,
                                  u16* __restrict__ Th, u16* __restrict__ Tl,
                                  int nheads, int ld)
{
    int idx = blockIdx.x * blockDim.x + threadIdx.x;
    int d  = idx & 31;
    int sh = idx >> 5;
    int h  = sh % nheads;
    int s  = sh / nheads;
    if (s >= S_LEN) return;
    float c  = rope[s*128 + d];
    float sn = rope[s*128 + 64 + d];
    const float* p = T + (size_t)s * ld + h*HD + d;
    float x0 = p[0], x1 = p[32];
    float y0 = fmaf(x0, c, -x1*sn);
    float y1 = fmaf(x1, c,  x0*sn);
    int b = s*ld + h*HD + d;
    float l;
    u16 h0 = h_hi(y0, l);
    Th[b] = h0;
    if (Tl) Tl[b] = toh(l);
    u16 h1 = h_hi(y1, l);
    Th[b + 32] = h1;
    if (Tl) Tl[b + 32] = toh(l);
}

// ---------------------------------------------------------------------------
// fp16x2 flash attention. 128 q-rows x 1 head, 8 warps x 16 rows.
// KV tiles of 64, single hi plane each, double buffered.
// ---------------------------------------------------------------------------
#define QSTR 144
#define KVPL (64*QSTR)           // 9216
#define KVBUF (2*KVPL)           // 18432 per buffer (Kh + Vh)
#define ATT_DYN (2*KVBUF)        // 36864 (covers Q staging: 2*128*QSTR = 36864)

__global__ __launch_bounds__(256)
void attn_kernel(const u16* __restrict__ Qh, const u16* __restrict__ Ql,
                 const u16* __restrict__ Kh, const u16* __restrict__ Vth,
                 const float* __restrict__ sinks,
                 u16* __restrict__ AOh, u16* __restrict__ AOl)
{
    extern __shared__ char sm[];
    const uint32_t sb = (uint32_t)__cvta_generic_to_shared(sm);

    const int h    = blockIdx.y;
    const int qi   = (int)gridDim.x - 1 - (int)blockIdx.x;
    const int s0   = qi * 128;
    const int kvh  = h >> 2;
    const int tid  = threadIdx.x;
    const int w    = tid >> 5;
    const int lane = tid & 31;
    const int g    = lane >> 2;
    const int t    = lane & 3;
    const int wrow = w * 16;

    // ---- stage Q hi/lo tiles via cp.async, extract A-fragments ----
    {
        const int r    = tid >> 1;
        const int half = tid & 1;
        const u16* qgh = Qh + (size_t)(s0 + r) * QDIM + h*HD + half*32;
        const u16* qgl = Ql + (size_t)(s0 + r) * QDIM + h*HD + half*32;
        const uint32_t d = sb + (uint32_t)(r * QSTR + half*64);
        #pragma unroll
        for (int i = 0; i < 4; ++i) {
            cp16(d + 16*i, qgh + 8*i);
            cp16(d + 128*QSTR + 16*i, qgl + 8*i);
        }
        cp_commit();
        cp_wait0();
    }
    __syncthreads();

    uint32_t qh[4][4], ql[4][4];
    #pragma unroll
    for (int kt = 0; kt < 4; ++kt) {
        uint32_t addr = sb + (uint32_t)((wrow + (lane & 15)) * QSTR) + kt*32 + ((lane >> 4) * 16);
        ldsm4(qh[kt][0], qh[kt][1], qh[kt][2], qh[kt][3], addr);
        ldsm4(ql[kt][0], ql[kt][1], ql[kt][2], ql[kt][3], addr + 128*QSTR);
    }
    __syncthreads();   // Q region reused for KV buffers below

    float m0 = -CUDART_INF_F, m1 = -CUDART_INF_F;
    float l0 = 0.f, l1 = 0.f;
    float o[8][4];
    #pragma unroll
    for (int nt = 0; nt < 8; ++nt)
        #pragma unroll
        for (int e = 0; e < 4; ++e) o[nt][e] = 0.f;

    const float scale = 0.125f;
    const int kb_end = 2*qi + 2;

    // loader mapping (per tile: 2 cp16 K + 2 cp16 V per thread)
    const int lrr = tid >> 2;
    const int lq4 = tid & 3;
    const u16* kg0 = Kh  + (size_t)lrr * KVDIM + kvh*HD + lq4*16;
    const u16* vg0 = Vth + (size_t)(kvh*HD + lrr) * S_LEN + lq4*16;
    const uint32_t ldd = (uint32_t)(lrr * QSTR + lq4*32);

    // prologue: tile 0 -> buf 0
    {
        cp16(sb + ldd,             kg0);
        cp16(sb + ldd + 16,        kg0 + 8);
        cp16(sb + KVPL + ldd,      vg0);
        cp16(sb + KVPL + ldd + 16, vg0 + 8);
        cp_commit();
    }

    for (int kb = 0; kb < kb_end; ++kb) {
        const int cur = kb & 1;
        if (kb + 1 < kb_end) {
            const int ks1 = (kb + 1) * 64;
            const uint32_t o2 = sb + (cur ^ 1) * KVBUF + ldd;
            cp16(o2,             kg0 + (size_t)ks1 * KVDIM);
            cp16(o2 + 16,        kg0 + (size_t)ks1 * KVDIM + 8);
            cp16(o2 + KVPL,      vg0 + ks1);
            cp16(o2 + KVPL + 16, vg0 + ks1 + 8);
            cp_commit();
            asm volatile("cp.async.wait_group 1;\n");
        } else {
            cp_wait0();
        }
        __syncthreads();

        const int ks0 = kb * 64;
        const uint32_t sK = sb + cur * KVBUF;
        const uint32_t sV = sK + KVPL;

        const bool skip = (ks0 > s0 + wrow + 15);
        if (!skip) {
            // ---- S = Q K^T (2 passes) ----
            float s[8][4];
            #pragma unroll
            for (int nt = 0; nt < 8; ++nt)
                #pragma unroll
                for (int e = 0; e < 4; ++e) s[nt][e] = 0.f;

            #pragma unroll
            for (int kt = 0; kt < 4; ++kt) {
                uint32_t bh[8][2];
                #pragma unroll
                for (int p = 0; p < 4; ++p) {
                    uint32_t addr = sK + (uint32_t)((p*16 + (lane & 7) + ((lane >> 4) << 3)) * QSTR)
                                  + kt*32 + (((lane >> 3) & 1) * 16);
                    ldsm4(bh[2*p][0], bh[2*p][1], bh[2*p+1][0], bh[2*p+1][1], addr);
                }
                #pragma unroll
                for (int nt = 0; nt < 8; ++nt) {
                    mma_f16(s[nt], qh[kt][0], qh[kt][1], qh[kt][2], qh[kt][3], bh[nt][0], bh[nt][1]);
                    mma_f16(s[nt], ql[kt][0], ql[kt][1], ql[kt][2], ql[kt][3], bh[nt][0], bh[nt][1]);
                }
            }

            // ---- scale + causal mask ----
            const bool need_mask = (ks0 + 63 > s0 + wrow);
            const int row0g = s0 + wrow + g;
            #pragma unroll
            for (int nt = 0; nt < 8; ++nt) {
                #pragma unroll
                for (int e = 0; e < 4; ++e) s[nt][e] *= scale;
                if (need_mask) {
                    const int c = ks0 + nt*8 + 2*t;
                    if (c     > row0g    ) s[nt][0] = -CUDART_INF_F;
                    if (c + 1 > row0g    ) s[nt][1] = -CUDART_INF_F;
                    if (c     > row0g + 8) s[nt][2] = -CUDART_INF_F;
                    if (c + 1 > row0g + 8) s[nt][3] = -CUDART_INF_F;
                }
            }

            // ---- online softmax ----
            float mx0 = -CUDART_INF_F, mx1 = -CUDART_INF_F;
            #pragma unroll
            for (int nt = 0; nt < 8; ++nt) {
                mx0 = fmaxf(mx0, fmaxf(s[nt][0], s[nt][1]));
                mx1 = fmaxf(mx1, fmaxf(s[nt][2], s[nt][3]));
            }
            mx0 = fmaxf(mx0, __shfl_xor_sync(0xffffffffu, mx0, 1));
            mx0 = fmaxf(mx0, __shfl_xor_sync(0xffffffffu, mx0, 2));
            mx1 = fmaxf(mx1, __shfl_xor_sync(0xffffffffu, mx1, 1));
            mx1 = fmaxf(mx1, __shfl_xor_sync(0xffffffffu, mx1, 2));

            float mn0 = fmaxf(m0, mx0), mn1 = fmaxf(m1, mx1);
            float corr0 = __expf(m0 - mn0), corr1 = __expf(m1 - mn1);

            float ps0 = 0.f, ps1 = 0.f;
            #pragma unroll
            for (int nt = 0; nt < 8; ++nt) {
                s[nt][0] = __expf(s[nt][0] - mn0);
                s[nt][1] = __expf(s[nt][1] - mn0);
                s[nt][2] = __expf(s[nt][2] - mn1);
                s[nt][3] = __expf(s[nt][3] - mn1);
                ps0 += s[nt][0] + s[nt][1];
                ps1 += s[nt][2] + s[nt][3];
            }
            ps0 += __shfl_xor_sync(0xffffffffu, ps0, 1);
            ps0 += __shfl_xor_sync(0xffffffffu, ps0, 2);
            ps1 += __shfl_xor_sync(0xffffffffu, ps1, 1);
            ps1 += __shfl_xor_sync(0xffffffffu, ps1, 2);

            l0 = l0 * corr0 + ps0;  m0 = mn0;
            l1 = l1 * corr1 + ps1;  m1 = mn1;

            #pragma unroll
            for (int nt = 0; nt < 8; ++nt) {
                o[nt][0] *= corr0; o[nt][1] *= corr0;
                o[nt][2] *= corr1; o[nt][3] *= corr1;
            }

            // ---- PV (2 passes, P hi/lo split in regs) ----
            #pragma unroll
            for (int kt = 0; kt < 4; ++kt) {
                float r0, r1;
                uint32_t ah0 = hsplit2(s[2*kt  ][0], s[2*kt  ][1], r0, r1);
                uint32_t al0 = hpack2(r0, r1);
                uint32_t ah1 = hsplit2(s[2*kt  ][2], s[2*kt  ][3], r0, r1);
                uint32_t al1 = hpack2(r0, r1);
                uint32_t ah2 = hsplit2(s[2*kt+1][0], s[2*kt+1][1], r0, r1);
                uint32_t al2 = hpack2(r0, r1);
                uint32_t ah3 = hsplit2(s[2*kt+1][2], s[2*kt+1][3], r0, r1);
                uint32_t al3 = hpack2(r0, r1);

                uint32_t vh[8][2];
                #pragma unroll
                for (int p = 0; p < 4; ++p) {
                    uint32_t addr = sV + (uint32_t)((p*16 + (lane & 7) + ((lane >> 4) << 3)) * QSTR)
                                  + kt*32 + (((lane >> 3) & 1) * 16);
                    ldsm4(vh[2*p][0], vh[2*p][1], vh[2*p+1][0], vh[2*p+1][1], addr);
                }
                #pragma unroll
                for (int nt = 0; nt < 8; ++nt) {
                    mma_f16(o[nt], ah0, ah1, ah2, ah3, vh[nt][0], vh[nt][1]);
                    mma_f16(o[nt], al0, al1, al2, al3, vh[nt][0], vh[nt][1]);
                }
            }
        }
        __syncthreads();
    }

    // ---- epilogue: sink-LSE renorm + split-store AO planes (fp16) ----
    const float sink = sinks[h];
    float lse0 = m0 + __logf(l0);
    float lse1 = m1 + __logf(l1);
    float cb0 = fmaxf(lse0, sink) + log1pf(__expf(-fabsf(lse0 - sink)));
    float cb1 = fmaxf(lse1, sink) + log1pf(__expf(-fabsf(lse1 - sink)));
    float inv0 = __expf(fmaxf(lse0 - cb0, -20.f)) / l0;
    float inv1 = __expf(fmaxf(lse1 - cb1, -20.f)) / l1;

    const int r0i = s0 + wrow + g;
    #pragma unroll
    for (int nt = 0; nt < 8; ++nt) {
        const int c = h*HD + nt*8 + 2*t;
        const size_t i0 = (size_t)r0i * QDIM + c;
        const size_t i1 = (size_t)(r0i + 8) * QDIM + c;
        float lr0, lr1;
        float v00 = o[nt][0] * inv0, v01 = o[nt][1] * inv0;
        float v10 = o[nt][2] * inv1, v11 = o[nt][3] * inv1;
        u16 h00 = h_hi(v00, lr0); u16 h01 = h_hi(v01, lr1);
        *(uint32_t*)(AOh + i0) = (uint32_t)h00 | ((uint32_t)h01 << 16);
        *(uint32_t*)(AOl + i0) = (uint32_t)toh(lr0) | ((uint32_t)toh(lr1) << 16);
        u16 h10 = h_hi(v10, lr0); u16 h11 = h_hi(v11, lr1);
        *(uint32_t*)(AOh + i1) = (uint32_t)h10 | ((uint32_t)h11 << 16);
        *(uint32_t*)(AOl + i1) = (uint32_t)toh(lr0) | ((uint32_t)toh(lr1) << 16);
    }
}

// ---------------------------------------------------------------------------
// Launch
// ---------------------------------------------------------------------------
extern "C" void kernel_launch(void* const* d_in, const int* in_sizes, int n_in,
                              void* d_out, int out_size)
{
    const float* x     = (const float*)d_in[0];
    const float* rope  = (const float*)d_in[1];
    const float* wq_w  = (const float*)d_in[2];
    const float* wq_b  = (const float*)d_in[3];
    const float* wk_w  = (const float*)d_in[4];
    const float* wk_b  = (const float*)d_in[5];
    const float* wv_w  = (const float*)d_in[6];
    const float* wv_b  = (const float*)d_in[7];
    const float* wo_w  = (const float*)d_in[8];
    const float* wo_b  = (const float*)d_in[9];
    const float* sinks = (const float*)d_in[10];
    float* out = (float*)d_out;

#define SYM(p, s) do { void* _q; cudaGetSymbolAddress(&_q, s); p = decltype(p)(_q); } while (0)
    float *Q, *K;
    u16 *Qh,*Ql,*Kh,*Vth,*AOh,*AOl,*xh,*xl,*wqh,*wkh,*wvh,*woh;
    SYM(Q, g_Q);   SYM(K, g_K);
    SYM(Qh, g_Qh); SYM(Ql, g_Ql); SYM(Kh, g_Kh);
    SYM(Vth, g_Vth);
    SYM(AOh, g_AOh); SYM(AOl, g_AOl);
    SYM(xh, g_xh); SYM(xl, g_xl);
    SYM(wqh, g_wqh); SYM(wkh, g_wkh); SYM(wvh, g_wvh); SYM(woh, g_woh);
#undef SYM

    cudaFuncSetAttribute(gemm_f16, cudaFuncAttributeMaxDynamicSharedMemorySize, GEMM_DYN);

    // convert inputs to fp16 planes
    split16_kernel<<<(S_LEN*DIM/4 + 255)/256, 256>>>(x, xh, xl, S_LEN*DIM/4);
    conv16_kernel<<<(QDIM*DIM/4  + 255)/256, 256>>>(wq_w, wqh, QDIM*DIM/4);
    conv16_kernel<<<(KVDIM*DIM/4 + 255)/256, 256>>>(wk_w, wkh, KVDIM*DIM/4);
    conv16_kernel<<<(KVDIM*DIM/4 + 255)/256, 256>>>(wv_w, wvh, KVDIM*DIM/4);
    conv16_kernel<<<(DIM*QDIM/4  + 255)/256, 256>>>(wo_w, woh, DIM*QDIM/4);

    // fused QKV projection: blocks 0-15 Q, 16-19 K, 20-23 V
    gemm_f16<<<dim3(24, S_LEN/128), 256, GEMM_DYN>>>(
        xh, xl,
        wqh, wq_b, Q, QDIM, 16,
        wkh, wk_b, K, KVDIM, 4,
        wvh, wv_b, Vth);

    // rope + fp16 split
    rope_split_kernel<<<(S_LEN*NH  *32)/256, 256>>>(Q, rope, Qh, Ql, NH,   QDIM);
    rope_split_kernel<<<(S_LEN*NKVH*32)/256, 256>>>(K, rope, Kh, nullptr, NKVH, KVDIM);

    // attention
    attn_kernel<<<dim3(S_LEN/128, NH), 256, ATT_DYN>>>(Qh, Ql, Kh, Vth, sinks, AOh, AOl);

    // output projection
    gemm_f16<<<dim3(16, S_LEN/128), 256, GEMM_DYN>>>(
        AOh, AOl,
        woh, wo_b, out, DIM, 16,
        nullptr, nullptr, nullptr, 0, 0,
        nullptr, nullptr, nullptr);
}

// round 17
// speedup vs baseline: 2.7029x; 1.6207x over previous
#include <cuda_runtime.h>
#include <cuda_fp16.h>
#include <math_constants.h>
#include <cstdint>

#define S_LEN 2048
#define DIM   2048
#define NH    32
#define NKVH  8
#define HD    64
#define QDIM  2048
#define KVDIM 512

typedef unsigned short u16;

// ---------------------------------------------------------------------------
// Scratch (fp16 planes)
// ---------------------------------------------------------------------------
__device__ __align__(16) float g_Q [S_LEN*QDIM];
__device__ __align__(16) float g_K [S_LEN*KVDIM];
__device__ __align__(16) u16 g_Qh[S_LEN*QDIM];
__device__ __align__(16) u16 g_Ql[S_LEN*QDIM];
__device__ __align__(16) u16 g_Kh[S_LEN*KVDIM];
__device__ __align__(16) u16 g_Vth[KVDIM*S_LEN];
__device__ __align__(16) u16 g_AOh[S_LEN*QDIM];
__device__ __align__(16) u16 g_AOl[S_LEN*QDIM];
__device__ __align__(16) u16 g_xh[S_LEN*DIM];
__device__ __align__(16) u16 g_xl[S_LEN*DIM];
__device__ __align__(16) u16 g_wqh[QDIM*DIM];
__device__ __align__(16) u16 g_wkh[KVDIM*DIM];
__device__ __align__(16) u16 g_wvh[KVDIM*DIM];
__device__ __align__(16) u16 g_woh[DIM*QDIM];

// ---------------------------------------------------------------------------
// fp16 helpers
// ---------------------------------------------------------------------------
__device__ __forceinline__ u16 toh(float x) {
    return __half_as_ushort(__float2half_rn(x));
}
__device__ __forceinline__ u16 h_hi(float x, float& lo) {
    u16 h = toh(x);
    lo = x - __half2float(__ushort_as_half(h));
    return h;
}
__device__ __forceinline__ uint32_t hsplit2(float a, float b, float& ra, float& rb)
{
    u16 ha = h_hi(a, ra);
    u16 hb = h_hi(b, rb);
    return ((uint32_t)hb << 16) | (uint32_t)ha;
}
__device__ __forceinline__ uint32_t hpack2(float a, float b)
{
    return ((uint32_t)toh(b) << 16) | (uint32_t)toh(a);
}

__device__ __forceinline__ void mma_f16(float c[4],
    uint32_t a0, uint32_t a1, uint32_t a2, uint32_t a3,
    uint32_t b0, uint32_t b1)
{
    asm volatile(
        "mma.sync.aligned.m16n8k16.row.col.f32.f16.f16.f32 "
        "{%0,%1,%2,%3}, {%4,%5,%6,%7}, {%8,%9}, {%0,%1,%2,%3};"
        : "+f"(c[0]), "+f"(c[1]), "+f"(c[2]), "+f"(c[3])
        : "r"(a0), "r"(a1), "r"(a2), "r"(a3), "r"(b0), "r"(b1));
}

__device__ __forceinline__ void ldsm4(uint32_t& r0, uint32_t& r1,
                                      uint32_t& r2, uint32_t& r3, uint32_t addr)
{
    asm volatile("ldmatrix.sync.aligned.m8n8.x4.shared.b16 {%0,%1,%2,%3}, [%4];"
        : "=r"(r0), "=r"(r1), "=r"(r2), "=r"(r3) : "r"(addr));
}
__device__ __forceinline__ void cp16(uint32_t dst, const void* src)
{
    asm volatile("cp.async.cg.shared.global [%0], [%1], 16;\n" :: "r"(dst), "l"(src));
}
__device__ __forceinline__ void cp_commit() { asm volatile("cp.async.commit_group;\n"); }
__device__ __forceinline__ void cp_wait0()  { asm volatile("cp.async.wait_group 0;\n"); }

// ---------------------------------------------------------------------------
// split16 / conv16
// ---------------------------------------------------------------------------
__global__ void split16_kernel(const float* __restrict__ in, u16* __restrict__ hi,
                               u16* __restrict__ lo, int n4)
{
    int i = blockIdx.x * blockDim.x + threadIdx.x;
    if (i >= n4) return;
    float4 v = ((const float4*)in)[i];
    float l0, l1, l2, l3;
    ushort4 H, L;
    H.x = h_hi(v.x, l0); H.y = h_hi(v.y, l1);
    H.z = h_hi(v.z, l2); H.w = h_hi(v.w, l3);
    L.x = toh(l0); L.y = toh(l1); L.z = toh(l2); L.w = toh(l3);
    ((ushort4*)hi)[i] = H;
    ((ushort4*)lo)[i] = L;
}

__global__ void conv16_kernel(const float* __restrict__ in, u16* __restrict__ hi, int n4)
{
    int i = blockIdx.x * blockDim.x + threadIdx.x;
    if (i >= n4) return;
    float4 v = ((const float4*)in)[i];
    ushort4 H;
    H.x = toh(v.x); H.y = toh(v.y); H.z = toh(v.z); H.w = toh(v.w);
    ((ushort4*)hi)[i] = H;
}

// ---------------------------------------------------------------------------
// fp16x2 NT GEMM (2 passes):  C = A * B^T + bias
// BM=BN=128, BK=32, 256 threads, __launch_bounds__(256,2).
// al fragments staged after pass 1 to cut peak registers.
// ---------------------------------------------------------------------------
#define GASTR 80
#define GPL   (128*GASTR)       // 10240
#define GBUF  (3*GPL)           // 30720
#define GEMM_DYN (2*GBUF)       // 61440

__global__ __launch_bounds__(256, 2)
void gemm_f16(const u16* __restrict__ Ah, const u16* __restrict__ Al,
              const u16* B_q, const float* bq, float* Cq, int ldcq, int nbq,
              const u16* B_k, const float* bk, float* Ck, int ldck, int nbk,
              const u16* B_v, const float* bv, u16* Vh)
{
    extern __shared__ char smdyn[];
    const uint32_t sbase = (uint32_t)__cvta_generic_to_shared(smdyn);

    const int tid  = threadIdx.x;
    const int wid  = tid >> 5;
    const int lane = tid & 31;
    const int g    = lane >> 2;
    const int t    = lane & 3;
    const int wm   = (wid & 1) * 64;
    const int wn   = (wid >> 1) * 32;
    const int row0 = blockIdx.y * 128;

    const u16* B; const float* bias;
    float* C = nullptr; int ldc = 0; bool vmode = false;
    int bx = blockIdx.x;
    if (bx < nbq)            { B = B_q; bias = bq; C = Cq; ldc = ldcq; }
    else if (bx < nbq + nbk) { bx -= nbq;       B = B_k; bias = bk; C = Ck; ldc = ldck; }
    else                     { bx -= nbq + nbk; B = B_v; bias = bv; vmode = true; }
    const int col0 = bx * 128;

    const int lr   = tid >> 1;
    const int half = tid & 1;
    const u16* Agh = Ah + (size_t)(row0 + lr) * 2048 + half*16;
    const u16* Agl = Al + (size_t)(row0 + lr) * 2048 + half*16;
    const u16* Bg  = B  + (size_t)(col0 + lr) * 2048 + half*16;
    const uint32_t ddst = (uint32_t)(lr * GASTR + half*32);

    float acc[4][4][4];
    #pragma unroll
    for (int mt = 0; mt < 4; ++mt)
        #pragma unroll
        for (int nt = 0; nt < 4; ++nt)
            #pragma unroll
            for (int e = 0; e < 4; ++e) acc[mt][nt][e] = 0.f;

    const int T = 2048 / 32;

    {
        const uint32_t o = sbase + ddst;
        cp16(o,              Agh);  cp16(o + 16,           Agh + 8);
        cp16(o + GPL,        Agl);  cp16(o + GPL + 16,     Agl + 8);
        cp16(o + 2*GPL,      Bg );  cp16(o + 2*GPL + 16,   Bg  + 8);
        cp_commit();
    }

    for (int tt = 0; tt < T; ++tt) {
        const int cur = tt & 1;
        if (tt + 1 < T) {
            const int k0 = (tt + 1) * 32;
            const uint32_t o = sbase + (cur ^ 1) * GBUF + ddst;
            cp16(o,            Agh + k0);  cp16(o + 16,          Agh + k0 + 8);
            cp16(o + GPL,      Agl + k0);  cp16(o + GPL + 16,    Agl + k0 + 8);
            cp16(o + 2*GPL,    Bg  + k0);  cp16(o + 2*GPL + 16,  Bg  + k0 + 8);
            cp_commit();
            asm volatile("cp.async.wait_group 1;\n");
        } else {
            cp_wait0();
        }
        __syncthreads();

        const uint32_t bufA = sbase + cur * GBUF;
        const uint32_t bufB = bufA + 2*GPL;

        #pragma unroll
        for (int kk = 0; kk < 2; ++kk) {
            const uint32_t kof = kk * 32;
            uint32_t bh[4][2];
            #pragma unroll
            for (int p = 0; p < 2; ++p) {
                uint32_t addr = bufB + (uint32_t)((wn + p*16 + (lane & 7) + ((lane >> 4) << 3)) * GASTR)
                              + kof + (((lane >> 3) & 1) * 16);
                ldsm4(bh[2*p][0], bh[2*p][1], bh[2*p+1][0], bh[2*p+1][1], addr);
            }
            // pass 1: hi(A) * B
            {
                uint32_t ah[4][4];
                #pragma unroll
                for (int mt = 0; mt < 4; ++mt) {
                    uint32_t addr = bufA + (uint32_t)((wm + mt*16 + (lane & 15)) * GASTR)
                                  + kof + ((lane >> 4) * 16);
                    ldsm4(ah[mt][0], ah[mt][1], ah[mt][2], ah[mt][3], addr);
                }
                #pragma unroll
                for (int mt = 0; mt < 4; ++mt)
                    #pragma unroll
                    for (int nt = 0; nt < 4; ++nt)
                        mma_f16(acc[mt][nt], ah[mt][0], ah[mt][1], ah[mt][2], ah[mt][3],
                                bh[nt][0], bh[nt][1]);
            }
            // pass 2: lo(A) * B
            {
                uint32_t al[4][4];
                #pragma unroll
                for (int mt = 0; mt < 4; ++mt) {
                    uint32_t addr = bufA + GPL + (uint32_t)((wm + mt*16 + (lane & 15)) * GASTR)
                                  + kof + ((lane >> 4) * 16);
                    ldsm4(al[mt][0], al[mt][1], al[mt][2], al[mt][3], addr);
                }
                #pragma unroll
                for (int mt = 0; mt < 4; ++mt)
                    #pragma unroll
                    for (int nt = 0; nt < 4; ++nt)
                        mma_f16(acc[mt][nt], al[mt][0], al[mt][1], al[mt][2], al[mt][3],
                                bh[nt][0], bh[nt][1]);
            }
        }
        __syncthreads();
    }

    #pragma unroll
    for (int mt = 0; mt < 4; ++mt) {
        const int r = row0 + wm + mt*16 + g;
        #pragma unroll
        for (int nt = 0; nt < 4; ++nt) {
            const int c = col0 + wn + nt*8 + 2*t;
            float v00 = acc[mt][nt][0] + bias[c];
            float v01 = acc[mt][nt][1] + bias[c+1];
            float v10 = acc[mt][nt][2] + bias[c];
            float v11 = acc[mt][nt][3] + bias[c+1];
            if (!vmode) {
                *(float2*)&C[(size_t)r       * ldc + c] = make_float2(v00, v01);
                *(float2*)&C[(size_t)(r + 8) * ldc + c] = make_float2(v10, v11);
            } else {
                Vh[(size_t)c     * S_LEN + r    ] = toh(v00);
                Vh[(size_t)(c+1) * S_LEN + r    ] = toh(v01);
                Vh[(size_t)c     * S_LEN + r + 8] = toh(v10);
                Vh[(size_t)(c+1) * S_LEN + r + 8] = toh(v11);
            }
        }
    }
}

// ---------------------------------------------------------------------------
// RoPE + split
// ---------------------------------------------------------------------------
__global__ void rope_split_kernel(const float* __restrict__ T, const float* __restrict__ rope,
                                  u16* __restrict__ Th, u16* __restrict__ Tl,
                                  int nheads, int ld)
{
    int idx = blockIdx.x * blockDim.x + threadIdx.x;
    int d  = idx & 31;
    int sh = idx >> 5;
    int h  = sh % nheads;
    int s  = sh / nheads;
    if (s >= S_LEN) return;
    float c  = rope[s*128 + d];
    float sn = rope[s*128 + 64 + d];
    const float* p = T + (size_t)s * ld + h*HD + d;
    float x0 = p[0], x1 = p[32];
    float y0 = fmaf(x0, c, -x1*sn);
    float y1 = fmaf(x1, c,  x0*sn);
    int b = s*ld + h*HD + d;
    float l;
    u16 h0 = h_hi(y0, l);
    Th[b] = h0;
    if (Tl) Tl[b] = toh(l);
    u16 h1 = h_hi(y1, l);
    Th[b + 32] = h1;
    if (Tl) Tl[b + 32] = toh(l);
}

// ---------------------------------------------------------------------------
// fp16x2 flash attention. Q planes persistent in smem (no persistent regs),
// Q fragments loaded JIT per kt. __launch_bounds__(256, 2).
// Smem: Q region [0, 36864) ; KV double buffer [36864, 73728).
// ---------------------------------------------------------------------------
#define QSTR 144
#define QOFF (2*128*QSTR)        // 36864: Q hi plane + Q lo plane
#define KVPL (64*QSTR)           // 9216
#define KVBUF (2*KVPL)           // 18432 per buffer (Kh + Vh)
#define ATT_DYN (QOFF + 2*KVBUF) // 73728

__global__ __launch_bounds__(256, 2)
void attn_kernel(const u16* __restrict__ Qh, const u16* __restrict__ Ql,
                 const u16* __restrict__ Kh, const u16* __restrict__ Vth,
                 const float* __restrict__ sinks,
                 u16* __restrict__ AOh, u16* __restrict__ AOl)
{
    extern __shared__ char sm[];
    const uint32_t sb  = (uint32_t)__cvta_generic_to_shared(sm);
    const uint32_t skv = sb + QOFF;

    const int h    = blockIdx.y;
    const int qi   = (int)gridDim.x - 1 - (int)blockIdx.x;
    const int s0   = qi * 128;
    const int kvh  = h >> 2;
    const int tid  = threadIdx.x;
    const int w    = tid >> 5;
    const int lane = tid & 31;
    const int g    = lane >> 2;
    const int t    = lane & 3;
    const int wrow = w * 16;

    // ---- stage Q hi/lo tiles via cp.async into dedicated region ----
    {
        const int r    = tid >> 1;
        const int half = tid & 1;
        const u16* qgh = Qh + (size_t)(s0 + r) * QDIM + h*HD + half*32;
        const u16* qgl = Ql + (size_t)(s0 + r) * QDIM + h*HD + half*32;
        const uint32_t d = sb + (uint32_t)(r * QSTR + half*64);
        #pragma unroll
        for (int i = 0; i < 4; ++i) {
            cp16(d + 16*i, qgh + 8*i);
            cp16(d + 128*QSTR + 16*i, qgl + 8*i);
        }
        cp_commit();
    }

    float m0 = -CUDART_INF_F, m1 = -CUDART_INF_F;
    float l0 = 0.f, l1 = 0.f;
    float o[8][4];
    #pragma unroll
    for (int nt = 0; nt < 8; ++nt)
        #pragma unroll
        for (int e = 0; e < 4; ++e) o[nt][e] = 0.f;

    const float scale = 0.125f;
    const int kb_end = 2*qi + 2;

    // loader mapping
    const int lrr = tid >> 2;
    const int lq4 = tid & 3;
    const u16* kg0 = Kh  + (size_t)lrr * KVDIM + kvh*HD + lq4*16;
    const u16* vg0 = Vth + (size_t)(kvh*HD + lrr) * S_LEN + lq4*16;
    const uint32_t ldd = (uint32_t)(lrr * QSTR + lq4*32);

    // prologue: KV tile 0 -> buf 0 (same group as Q staging)
    {
        cp16(skv + ldd,             kg0);
        cp16(skv + ldd + 16,        kg0 + 8);
        cp16(skv + KVPL + ldd,      vg0);
        cp16(skv + KVPL + ldd + 16, vg0 + 8);
        cp_commit();
    }

    for (int kb = 0; kb < kb_end; ++kb) {
        const int cur = kb & 1;
        if (kb + 1 < kb_end) {
            const int ks1 = (kb + 1) * 64;
            const uint32_t o2 = skv + (cur ^ 1) * KVBUF + ldd;
            cp16(o2,             kg0 + (size_t)ks1 * KVDIM);
            cp16(o2 + 16,        kg0 + (size_t)ks1 * KVDIM + 8);
            cp16(o2 + KVPL,      vg0 + ks1);
            cp16(o2 + KVPL + 16, vg0 + ks1 + 8);
            cp_commit();
            asm volatile("cp.async.wait_group 1;\n");
        } else {
            cp_wait0();
        }
        __syncthreads();

        const int ks0 = kb * 64;
        const uint32_t sK = skv + cur * KVBUF;
        const uint32_t sV = sK + KVPL;

        const bool skip = (ks0 > s0 + wrow + 15);
        if (!skip) {
            // ---- S = Q K^T (2 passes, Q frags JIT from smem) ----
            float s[8][4];
            #pragma unroll
            for (int nt = 0; nt < 8; ++nt)
                #pragma unroll
                for (int e = 0; e < 4; ++e) s[nt][e] = 0.f;

            #pragma unroll
            for (int kt = 0; kt < 4; ++kt) {
                uint32_t qaddr = sb + (uint32_t)((wrow + (lane & 15)) * QSTR) + kt*32 + ((lane >> 4) * 16);
                uint32_t q0, q1, q2, q3, r0, r1, r2, r3;
                ldsm4(q0, q1, q2, q3, qaddr);
                ldsm4(r0, r1, r2, r3, qaddr + 128*QSTR);

                uint32_t bh[8][2];
                #pragma unroll
                for (int p = 0; p < 4; ++p) {
                    uint32_t addr = sK + (uint32_t)((p*16 + (lane & 7) + ((lane >> 4) << 3)) * QSTR)
                                  + kt*32 + (((lane >> 3) & 1) * 16);
                    ldsm4(bh[2*p][0], bh[2*p][1], bh[2*p+1][0], bh[2*p+1][1], addr);
                }
                #pragma unroll
                for (int nt = 0; nt < 8; ++nt) {
                    mma_f16(s[nt], q0, q1, q2, q3, bh[nt][0], bh[nt][1]);
                    mma_f16(s[nt], r0, r1, r2, r3, bh[nt][0], bh[nt][1]);
                }
            }

            // ---- scale + causal mask ----
            const bool need_mask = (ks0 + 63 > s0 + wrow);
            const int row0g = s0 + wrow + g;
            #pragma unroll
            for (int nt = 0; nt < 8; ++nt) {
                #pragma unroll
                for (int e = 0; e < 4; ++e) s[nt][e] *= scale;
                if (need_mask) {
                    const int c = ks0 + nt*8 + 2*t;
                    if (c     > row0g    ) s[nt][0] = -CUDART_INF_F;
                    if (c + 1 > row0g    ) s[nt][1] = -CUDART_INF_F;
                    if (c     > row0g + 8) s[nt][2] = -CUDART_INF_F;
                    if (c + 1 > row0g + 8) s[nt][3] = -CUDART_INF_F;
                }
            }

            // ---- online softmax ----
            float mx0 = -CUDART_INF_F, mx1 = -CUDART_INF_F;
            #pragma unroll
            for (int nt = 0; nt < 8; ++nt) {
                mx0 = fmaxf(mx0, fmaxf(s[nt][0], s[nt][1]));
                mx1 = fmaxf(mx1, fmaxf(s[nt][2], s[nt][3]));
            }
            mx0 = fmaxf(mx0, __shfl_xor_sync(0xffffffffu, mx0, 1));
            mx0 = fmaxf(mx0, __shfl_xor_sync(0xffffffffu, mx0, 2));
            mx1 = fmaxf(mx1, __shfl_xor_sync(0xffffffffu, mx1, 1));
            mx1 = fmaxf(mx1, __shfl_xor_sync(0xffffffffu, mx1, 2));

            float mn0 = fmaxf(m0, mx0), mn1 = fmaxf(m1, mx1);
            float corr0 = __expf(m0 - mn0), corr1 = __expf(m1 - mn1);

            float ps0 = 0.f, ps1 = 0.f;
            #pragma unroll
            for (int nt = 0; nt < 8; ++nt) {
                s[nt][0] = __expf(s[nt][0] - mn0);
                s[nt][1] = __expf(s[nt][1] - mn0);
                s[nt][2] = __expf(s[nt][2] - mn1);
                s[nt][3] = __expf(s[nt][3] - mn1);
                ps0 += s[nt][0] + s[nt][1];
                ps1 += s[nt][2] + s[nt][3];
            }
            ps0 += __shfl_xor_sync(0xffffffffu, ps0, 1);
            ps0 += __shfl_xor_sync(0xffffffffu, ps0, 2);
            ps1 += __shfl_xor_sync(0xffffffffu, ps1, 1);
            ps1 += __shfl_xor_sync(0xffffffffu, ps1, 2);

            l0 = l0 * corr0 + ps0;  m0 = mn0;
            l1 = l1 * corr1 + ps1;  m1 = mn1;

            #pragma unroll
            for (int nt = 0; nt < 8; ++nt) {
                o[nt][0] *= corr0; o[nt][1] *= corr0;
                o[nt][2] *= corr1; o[nt][3] *= corr1;
            }

            // ---- PV (2 passes, P hi/lo split in regs) ----
            #pragma unroll
            for (int kt = 0; kt < 4; ++kt) {
                float r0, r1;
                uint32_t ah0 = hsplit2(s[2*kt  ][0], s[2*kt  ][1], r0, r1);
                uint32_t al0 = hpack2(r0, r1);
                uint32_t ah1 = hsplit2(s[2*kt  ][2], s[2*kt  ][3], r0, r1);
                uint32_t al1 = hpack2(r0, r1);
                uint32_t ah2 = hsplit2(s[2*kt+1][0], s[2*kt+1][1], r0, r1);
                uint32_t al2 = hpack2(r0, r1);
                uint32_t ah3 = hsplit2(s[2*kt+1][2], s[2*kt+1][3], r0, r1);
                uint32_t al3 = hpack2(r0, r1);

                uint32_t vh[8][2];
                #pragma unroll
                for (int p = 0; p < 4; ++p) {
                    uint32_t addr = sV + (uint32_t)((p*16 + (lane & 7) + ((lane >> 4) << 3)) * QSTR)
                                  + kt*32 + (((lane >> 3) & 1) * 16);
                    ldsm4(vh[2*p][0], vh[2*p][1], vh[2*p+1][0], vh[2*p+1][1], addr);
                }
                #pragma unroll
                for (int nt = 0; nt < 8; ++nt) {
                    mma_f16(o[nt], ah0, ah1, ah2, ah3, vh[nt][0], vh[nt][1]);
                    mma_f16(o[nt], al0, al1, al2, al3, vh[nt][0], vh[nt][1]);
                }
            }
        }
        __syncthreads();
    }

    // ---- epilogue: sink-LSE renorm + split-store AO planes ----
    const float sink = sinks[h];
    float lse0 = m0 + __logf(l0);
    float lse1 = m1 + __logf(l1);
    float cb0 = fmaxf(lse0, sink) + log1pf(__expf(-fabsf(lse0 - sink)));
    float cb1 = fmaxf(lse1, sink) + log1pf(__expf(-fabsf(lse1 - sink)));
    float inv0 = __expf(fmaxf(lse0 - cb0, -20.f)) / l0;
    float inv1 = __expf(fmaxf(lse1 - cb1, -20.f)) / l1;

    const int r0i = s0 + wrow + g;
    #pragma unroll
    for (int nt = 0; nt < 8; ++nt) {
        const int c = h*HD + nt*8 + 2*t;
        const size_t i0 = (size_t)r0i * QDIM + c;
        const size_t i1 = (size_t)(r0i + 8) * QDIM + c;
        float lr0, lr1;
        float v00 = o[nt][0] * inv0, v01 = o[nt][1] * inv0;
        float v10 = o[nt][2] * inv1, v11 = o[nt][3] * inv1;
        u16 h00 = h_hi(v00, lr0); u16 h01 = h_hi(v01, lr1);
        *(uint32_t*)(AOh + i0) = (uint32_t)h00 | ((uint32_t)h01 << 16);
        *(uint32_t*)(AOl + i0) = (uint32_t)toh(lr0) | ((uint32_t)toh(lr1) << 16);
        u16 h10 = h_hi(v10, lr0); u16 h11 = h_hi(v11, lr1);
        *(uint32_t*)(AOh + i1) = (uint32_t)h10 | ((uint32_t)h11 << 16);
        *(uint32_t*)(AOl + i1) = (uint32_t)toh(lr0) | ((uint32_t)toh(lr1) << 16);
    }
}

// ---------------------------------------------------------------------------
// Launch
// ---------------------------------------------------------------------------
extern "C" void kernel_launch(void* const* d_in, const int* in_sizes, int n_in,
                              void* d_out, int out_size)
{
    const float* x     = (const float*)d_in[0];
    const float* rope  = (const float*)d_in[1];
    const float* wq_w  = (const float*)d_in[2];
    const float* wq_b  = (const float*)d_in[3];
    const float* wk_w  = (const float*)d_in[4];
    const float* wk_b  = (const float*)d_in[5];
    const float* wv_w  = (const float*)d_in[6];
    const float* wv_b  = (const float*)d_in[7];
    const float* wo_w  = (const float*)d_in[8];
    const float* wo_b  = (const float*)d_in[9];
    const float* sinks = (const float*)d_in[10];
    float* out = (float*)d_out;

#define SYM(p, s) do { void* _q; cudaGetSymbolAddress(&_q, s); p = decltype(p)(_q); } while (0)
    float *Q, *K;
    u16 *Qh,*Ql,*Kh,*Vth,*AOh,*AOl,*xh,*xl,*wqh,*wkh,*wvh,*woh;
    SYM(Q, g_Q);   SYM(K, g_K);
    SYM(Qh, g_Qh); SYM(Ql, g_Ql); SYM(Kh, g_Kh);
    SYM(Vth, g_Vth);
    SYM(AOh, g_AOh); SYM(AOl, g_AOl);
    SYM(xh, g_xh); SYM(xl, g_xl);
    SYM(wqh, g_wqh); SYM(wkh, g_wkh); SYM(wvh, g_wvh); SYM(woh, g_woh);
#undef SYM

    cudaFuncSetAttribute(gemm_f16, cudaFuncAttributeMaxDynamicSharedMemorySize, GEMM_DYN);
    cudaFuncSetAttribute(attn_kernel, cudaFuncAttributeMaxDynamicSharedMemorySize, ATT_DYN);

    // convert inputs to fp16 planes
    split16_kernel<<<(S_LEN*DIM/4 + 255)/256, 256>>>(x, xh, xl, S_LEN*DIM/4);
    conv16_kernel<<<(QDIM*DIM/4  + 255)/256, 256>>>(wq_w, wqh, QDIM*DIM/4);
    conv16_kernel<<<(KVDIM*DIM/4 + 255)/256, 256>>>(wk_w, wkh, KVDIM*DIM/4);
    conv16_kernel<<<(KVDIM*DIM/4 + 255)/256, 256>>>(wv_w, wvh, KVDIM*DIM/4);
    conv16_kernel<<<(DIM*QDIM/4  + 255)/256, 256>>>(wo_w, woh, DIM*QDIM/4);

    // fused QKV projection: blocks 0-15 Q, 16-19 K, 20-23 V
    gemm_f16<<<dim3(24, S_LEN/128), 256, GEMM_DYN>>>(
        xh, xl,
        wqh, wq_b, Q, QDIM, 16,
        wkh, wk_b, K, KVDIM, 4,
        wvh, wv_b, Vth);

    // rope + fp16 split
    rope_split_kernel<<<(S_LEN*NH  *32)/256, 256>>>(Q, rope, Qh, Ql, NH,   QDIM);
    rope_split_kernel<<<(S_LEN*NKVH*32)/256, 256>>>(K, rope, Kh, nullptr, NKVH, KVDIM);

    // attention
    attn_kernel<<<dim3(S_LEN/128, NH), 256, ATT_DYN>>>(Qh, Ql, Kh, Vth, sinks, AOh, AOl);

    // output projection
    gemm_f16<<<dim3(16, S_LEN/128), 256, GEMM_DYN>>>(
        AOh, AOl,
        woh, wo_b, out, DIM, 16,
        nullptr, nullptr, nullptr, 0, 0,
        nullptr, nullptr, nullptr);
}